// round 5
// baseline (speedup 1.0000x reference)
#include <cuda_runtime.h>

// Shapes (fixed per reference setup_inputs)
#define BB 8
#define II 32
#define OO 32
#define DD 8
#define HWX 196     // 14*14
#define KK 9
#define SLAB (DD*HWX*KK)          // 14112 floats per (b,i,o)
#define SITES (BB*OO*HWX)         // 50176 routing sites

// Scratch: x1 in [B,O,HW][I,D] layout, 12,845,056 floats = 51.4 MB
__device__ float4 g_x1[(size_t)SITES * II * DD / 4];

// ---------------------------------------------------------------------------
// Pass 1: per (b,i,o, half-of-h) block. Stage half slab in smem, then
// one thread per site computes the norm-weighted average over the 9 kernel
// positions and writes 8 floats (2x float4) into the site-major scratch.
// ---------------------------------------------------------------------------
__global__ void __launch_bounds__(128) pass1_kernel(const float* __restrict__ x) {
    __shared__ float sm[7056];                 // 8 d-chunks * 882 floats
    const int bio  = blockIdx.x;               // [0, B*I*O)
    const int half = blockIdx.y;               // 0 or 1  (h rows 0..6 / 7..13)

    // Per-d chunk is 1764 floats (882 float2); a half of it is 441 float2.
    const float2* src2 = (const float2*)x + (size_t)bio * (SLAB / 2) + half * 441;
    float2* sm2 = (float2*)sm;
    #pragma unroll
    for (int d = 0; d < DD; d++) {
        for (int r = threadIdx.x; r < 441; r += 128) {
            sm2[d * 441 + r] = src2[(size_t)d * 882 + r];
        }
    }
    __syncthreads();

    const int ls = threadIdx.x;                // local site within this half
    if (ls < 98) {
        float acc[DD];
        #pragma unroll
        for (int d = 0; d < DD; d++) acc[d] = 0.f;
        float wsum = 0.f;

        #pragma unroll
        for (int k = 0; k < KK; k++) {
            float tv[DD];
            float nk2 = 0.f;
            #pragma unroll
            for (int d = 0; d < DD; d++) {
                float t = sm[d * 882 + ls * KK + k];   // lane stride 9: conflict-free
                tv[d] = t;
                nk2 += t * t;
            }
            float nk = sqrtf(nk2);
            wsum += nk;
            #pragma unroll
            for (int d = 0; d < DD; d++) acc[d] += nk * tv[d];
        }
        float inv = 1.f / wsum;

        const int b = bio / (II * OO);
        const int i = (bio / OO) % II;
        const int o = bio % OO;
        const int site = (b * OO + o) * HWX + half * 98 + ls;

        float4 lo = make_float4(acc[0] * inv, acc[1] * inv, acc[2] * inv, acc[3] * inv);
        float4 hi = make_float4(acc[4] * inv, acc[5] * inv, acc[6] * inv, acc[7] * inv);
        size_t dst = (size_t)site * 64 + i * 2;        // float4 index
        g_x1[dst]     = lo;
        g_x1[dst + 1] = hi;
    }
}

// ---------------------------------------------------------------------------
// Pass 2: warp per site; lane = input capsule i.
//   1) n_i = ||x1_i||, butterfly-reduce S=sum n, T[d]=sum n*x1
//   2) v = T/S, loss_i = -(v . x1_i)
//   3) kthvalue select: choose_i <=> |{j: loss_j < loss_i}| <= 25
//   4) masked weighted average, lanes 0..7 write output
// ---------------------------------------------------------------------------
__global__ void __launch_bounds__(256) pass2_kernel(float* __restrict__ out) {
    const unsigned FULL = 0xffffffffu;
    const int site = (blockIdx.x * 256 + threadIdx.x) >> 5;
    const int lane = threadIdx.x & 31;

    const float4* p = g_x1 + (size_t)site * 64 + lane * 2;
    float4 lo = p[0], hi = p[1];
    float xv[8] = {lo.x, lo.y, lo.z, lo.w, hi.x, hi.y, hi.z, hi.w};

    float n2 = 0.f;
    #pragma unroll
    for (int d = 0; d < 8; d++) n2 += xv[d] * xv[d];
    float n = sqrtf(n2);

    float S = n;
    float T[8];
    #pragma unroll
    for (int d = 0; d < 8; d++) T[d] = n * xv[d];
    #pragma unroll
    for (int o = 16; o > 0; o >>= 1) {
        S += __shfl_xor_sync(FULL, S, o);
        #pragma unroll
        for (int d = 0; d < 8; d++) T[d] += __shfl_xor_sync(FULL, T[d], o);
    }
    float invS = 1.f / S;

    float loss = 0.f;
    #pragma unroll
    for (int d = 0; d < 8; d++) loss -= (T[d] * invS) * xv[d];

    int c = 0;
    #pragma unroll
    for (int j = 0; j < 32; j++)
        c += (__shfl_sync(FULL, loss, j) < loss) ? 1 : 0;

    float m = (c <= 25) ? n : 0.f;      // subset_size = ceil(0.8*32) = 26 -> rank <= 25
    float S2 = m;
    float U[8];
    #pragma unroll
    for (int d = 0; d < 8; d++) U[d] = m * xv[d];
    #pragma unroll
    for (int o = 16; o > 0; o >>= 1) {
        S2 += __shfl_xor_sync(FULL, S2, o);
        #pragma unroll
        for (int d = 0; d < 8; d++) U[d] += __shfl_xor_sync(FULL, U[d], o);
    }

    if (lane < 8) {
        float val = 0.f;
        #pragma unroll
        for (int d = 0; d < 8; d++) if (lane == d) val = U[d] / S2;
        const int bo = site / HWX;
        const int hw = site - bo * HWX;
        out[((size_t)bo * 8 + lane) * HWX + hw] = val;
    }
}

extern "C" void kernel_launch(void* const* d_in, const int* in_sizes, int n_in,
                              void* d_out, int out_size) {
    const float* x = (const float*)d_in[0];
    float* out = (float*)d_out;

    dim3 g1(BB * II * OO, 2);          // 8192 x 2 blocks, 128 threads
    pass1_kernel<<<g1, 128>>>(x);

    pass2_kernel<<<SITES / 8, 256>>>(out);   // 6272 blocks, warp per site
}

// round 15
// speedup vs baseline: 2.0534x; 2.0534x over previous
#include <cuda_runtime.h>
#include <cstdint>

// Shapes (fixed per reference setup_inputs)
#define BB 8
#define II 32
#define OO 32
#define DD 8
#define HWX 196     // 14*14
#define KK 9
#define SLAB (DD*HWX*KK)          // 14112 floats per (b,i,o)
#define SITES (BB*OO*HWX)         // 50176 routing sites

// Scratch: x1 in [B,O,HW][I,D] layout, 12,845,056 floats = 51.4 MB
__device__ float4 g_x1[(size_t)SITES * II * DD / 4];

__device__ __forceinline__ void cp_async8(unsigned smem_addr, const void* gptr) {
    asm volatile("cp.async.ca.shared.global [%0], [%1], 8;\n"
                 :: "r"(smem_addr), "l"(gptr));
}

// ---------------------------------------------------------------------------
// Pass 1: per (b,i,o, half-of-h) block. Stage half slab in smem via cp.async
// (high MLP, no register dependence), then one thread per site computes the
// norm-weighted average over the 9 kernel positions and writes 8 floats
// (2x float4) into the site-major scratch.
// ---------------------------------------------------------------------------
__global__ void __launch_bounds__(128) pass1_kernel(const float* __restrict__ x) {
    __shared__ float sm[7056];                 // 8 d-chunks * 882 floats
    const int bio  = blockIdx.x;               // [0, B*I*O)
    const int half = blockIdx.y;               // 0 or 1  (h rows 0..6 / 7..13)

    // Per-d chunk is 1764 floats (882 float2); a half of it is 441 float2.
    const float2* src2 = (const float2*)x + (size_t)bio * (SLAB / 2) + half * 441;
    unsigned smb = (unsigned)__cvta_generic_to_shared(sm);

    // Issue all ~28 8-byte copies per thread back-to-back (LDGSTS: no dest
    // register -> MLP limited only by queue depth, not by ptxas reg reuse).
    #pragma unroll
    for (int d = 0; d < DD; d++) {
        for (int r = threadIdx.x; r < 441; r += 128) {
            cp_async8(smb + (unsigned)(d * 441 + r) * 8u, src2 + (size_t)d * 882 + r);
        }
    }
    asm volatile("cp.async.commit_group;\n" ::: "memory");
    asm volatile("cp.async.wait_group 0;\n" ::: "memory");
    __syncthreads();

    const int ls = threadIdx.x;                // local site within this half
    if (ls < 98) {
        float acc[DD];
        #pragma unroll
        for (int d = 0; d < DD; d++) acc[d] = 0.f;
        float wsum = 0.f;

        #pragma unroll
        for (int k = 0; k < KK; k++) {
            float tv[DD];
            float nk2 = 0.f;
            #pragma unroll
            for (int d = 0; d < DD; d++) {
                float t = sm[d * 882 + ls * KK + k];   // lane stride 9: conflict-free
                tv[d] = t;
                nk2 += t * t;
            }
            float nk = sqrtf(nk2);
            wsum += nk;
            #pragma unroll
            for (int d = 0; d < DD; d++) acc[d] += nk * tv[d];
        }
        float inv = 1.f / wsum;

        const int b = bio / (II * OO);
        const int i = (bio / OO) % II;
        const int o = bio % OO;
        const int site = (b * OO + o) * HWX + half * 98 + ls;

        float4 lo = make_float4(acc[0] * inv, acc[1] * inv, acc[2] * inv, acc[3] * inv);
        float4 hi = make_float4(acc[4] * inv, acc[5] * inv, acc[6] * inv, acc[7] * inv);
        size_t dst = (size_t)site * 64 + i * 2;        // float4 index
        g_x1[dst]     = lo;
        g_x1[dst + 1] = hi;
    }
}

// ---------------------------------------------------------------------------
// Pass 2: warp per site; lane = input capsule i.  (unchanged, 29us measured)
// ---------------------------------------------------------------------------
__global__ void __launch_bounds__(256) pass2_kernel(float* __restrict__ out) {
    const unsigned FULL = 0xffffffffu;
    const int site = (blockIdx.x * 256 + threadIdx.x) >> 5;
    const int lane = threadIdx.x & 31;

    const float4* p = g_x1 + (size_t)site * 64 + lane * 2;
    float4 lo = p[0], hi = p[1];
    float xv[8] = {lo.x, lo.y, lo.z, lo.w, hi.x, hi.y, hi.z, hi.w};

    float n2 = 0.f;
    #pragma unroll
    for (int d = 0; d < 8; d++) n2 += xv[d] * xv[d];
    float n = sqrtf(n2);

    float S = n;
    float T[8];
    #pragma unroll
    for (int d = 0; d < 8; d++) T[d] = n * xv[d];
    #pragma unroll
    for (int o = 16; o > 0; o >>= 1) {
        S += __shfl_xor_sync(FULL, S, o);
        #pragma unroll
        for (int d = 0; d < 8; d++) T[d] += __shfl_xor_sync(FULL, T[d], o);
    }
    float invS = 1.f / S;

    float loss = 0.f;
    #pragma unroll
    for (int d = 0; d < 8; d++) loss -= (T[d] * invS) * xv[d];

    int c = 0;
    #pragma unroll
    for (int j = 0; j < 32; j++)
        c += (__shfl_sync(FULL, loss, j) < loss) ? 1 : 0;

    float m = (c <= 25) ? n : 0.f;      // subset_size = ceil(0.8*32) = 26 -> rank <= 25
    float S2 = m;
    float U[8];
    #pragma unroll
    for (int d = 0; d < 8; d++) U[d] = m * xv[d];
    #pragma unroll
    for (int o = 16; o > 0; o >>= 1) {
        S2 += __shfl_xor_sync(FULL, S2, o);
        #pragma unroll
        for (int d = 0; d < 8; d++) U[d] += __shfl_xor_sync(FULL, U[d], o);
    }

    if (lane < 8) {
        float val = 0.f;
        #pragma unroll
        for (int d = 0; d < 8; d++) if (lane == d) val = U[d] / S2;
        const int bo = site / HWX;
        const int hw = site - bo * HWX;
        out[((size_t)bo * 8 + lane) * HWX + hw] = val;
    }
}

extern "C" void kernel_launch(void* const* d_in, const int* in_sizes, int n_in,
                              void* d_out, int out_size) {
    const float* x = (const float*)d_in[0];
    float* out = (float*)d_out;

    dim3 g1(BB * II * OO, 2);          // 8192 x 2 blocks, 128 threads
    pass1_kernel<<<g1, 128>>>(x);

    pass2_kernel<<<SITES / 8, 256>>>(out);   // 6272 blocks, warp per site
}